// round 2
// baseline (speedup 1.0000x reference)
#include <cuda_runtime.h>
#include <cstdint>

// Problem constants (fixed by the reference): B=8, H=16, S=1024, D=64.
#define Bb 8
#define Hh 16
#define Ss 1024
#define Dd 64
#define BQ 32        // query rows per CTA
#define KT 64        // key tile
#define NTHREADS 256
#define SROW 1032    // padded smem stride for score tile (bank-conflict-free softmax)

struct K2 { uint32_t a, b; };

__host__ __device__ constexpr uint32_t rotl_c(uint32_t x, int r) {
    return (x << r) | (x >> (32 - r));
}

// Full 20-round threefry2x32, constexpr (for deriving the folded key at compile time).
constexpr K2 threefry_host(uint32_t k0, uint32_t k1, uint32_t c0, uint32_t c1) {
    uint32_t ks[3] = { k0, k1, 0x1BD11BDAu ^ k0 ^ k1 };
    uint32_t x0 = c0 + ks[0], x1 = c1 + ks[1];
    const int rot[8] = {13, 15, 26, 6, 17, 29, 16, 24};
    for (int g = 0; g < 5; ++g) {
        for (int i = 0; i < 4; ++i) {
            x0 += x1;
            x1 = rotl_c(x1, rot[(g & 1) * 4 + i]);
            x1 ^= x0;
        }
        x0 += ks[(g + 1) % 3];
        x1 += ks[(g + 2) % 3] + (uint32_t)(g + 1);
    }
    return { x0, x1 };
}

// Device threefry, JAX *partitionable* scheme (default in modern JAX):
//   element idx -> counter pair (hi32(idx), lo32(idx)) = (0, idx) for idx < 2^32
//   32-bit random bits = x0 ^ x1
__device__ __forceinline__ float jax_uniform(uint32_t idx, uint32_t k0, uint32_t k1) {
    const uint32_t ks2 = 0x1BD11BDAu ^ k0 ^ k1;
    uint32_t x0 = k0;           // c0 = 0
    uint32_t x1 = idx + k1;     // c1 = idx
#define TF_RND(r) { x0 += x1; x1 = __funnelshift_l(x1, x1, (r)); x1 ^= x0; }
    TF_RND(13) TF_RND(15) TF_RND(26) TF_RND(6)   x0 += k1;  x1 += ks2 + 1u;
    TF_RND(17) TF_RND(29) TF_RND(16) TF_RND(24)  x0 += ks2; x1 += k0 + 2u;
    TF_RND(13) TF_RND(15) TF_RND(26) TF_RND(6)   x0 += k0;  x1 += k1 + 3u;
    TF_RND(17) TF_RND(29) TF_RND(16) TF_RND(24)  x0 += k1;  x1 += ks2 + 4u;
    TF_RND(13) TF_RND(15) TF_RND(26) TF_RND(6)   x0 += ks2; x1 += k0 + 5u;
#undef TF_RND
    uint32_t bits = x0 ^ x1;
    return __uint_as_float((bits >> 9) | 0x3f800000u) - 1.0f;
}

// smem layout (floats):
//   sS : BQ * SROW        (score / attn tile, padded stride)
//   sQ : BQ * Dd          (query tile)
//   sT : KT * Dd          (K tile transposed [d][k] / V tile [k][d])
#define SMEM_FLOATS (BQ * SROW + BQ * Dd + KT * Dd)

extern "C" __global__ void __launch_bounds__(NTHREADS, 1)
attn_kernel(const float* __restrict__ Q, const float* __restrict__ Kt,
            const float* __restrict__ V, const int* __restrict__ M,
            float* __restrict__ Out, float* __restrict__ Attn,
            uint32_t rk0, uint32_t rk1)
{
    extern __shared__ float smem[];
    float* sS = smem;
    float* sQ = smem + BQ * SROW;
    float* sT = sQ + BQ * Dd;

    const int qt  = blockIdx.x;          // q tile (0..31)
    const int h   = blockIdx.y;
    const int b   = blockIdx.z;
    const int tid = threadIdx.x;
    const int bh  = b * Hh + h;

    const float* Qb = Q  + ((size_t)bh * Ss + qt * BQ) * Dd;
    const float* Kb = Kt + (size_t)bh * Ss * Dd;
    const float* Vb = V  + (size_t)bh * Ss * Dd;
    const int*   Mb = M  + ((size_t)b * Ss + qt * BQ) * Ss;  // mask broadcasts over H

    // Load Q tile (32x64 floats = 512 float4)
    {
        const float4* src = (const float4*)Qb;
        float4* dst = (float4*)sQ;
        for (int i = tid; i < BQ * Dd / 4; i += NTHREADS) dst[i] = src[i];
    }

    const int qp = tid >> 4;        // 0..15 -> q rows {2qp, 2qp+1}
    const int cg = tid & 15;        // 0..15 -> 4 cols at 4*cg within 64-wide tile
    const int q0 = qp * 2, q1 = q0 + 1;

    // ---------------- QK^T: scores into sS ----------------
    for (int kt = 0; kt < Ss / KT; ++kt) {
        __syncthreads();
        // load K tile transposed: sT[d][k]
        {
            const float4* src = (const float4*)(Kb + (size_t)kt * KT * Dd);
            for (int i = tid; i < KT * Dd / 4; i += NTHREADS) {
                float4 v = src[i];
                int row = i >> 4;           // key index in tile
                int d0  = (i & 15) * 4;
                sT[(d0 + 0) * KT + row] = v.x;
                sT[(d0 + 1) * KT + row] = v.y;
                sT[(d0 + 2) * KT + row] = v.z;
                sT[(d0 + 3) * KT + row] = v.w;
            }
        }
        __syncthreads();

        float acc[2][4] = {{0.f,0.f,0.f,0.f},{0.f,0.f,0.f,0.f}};
        #pragma unroll 16
        for (int d = 0; d < Dd; ++d) {
            float a0 = sQ[q0 * Dd + d];
            float a1 = sQ[q1 * Dd + d];
            float4 bv = ((const float4*)(sT + d * KT))[cg];
            acc[0][0] += a0 * bv.x; acc[0][1] += a0 * bv.y;
            acc[0][2] += a0 * bv.z; acc[0][3] += a0 * bv.w;
            acc[1][0] += a1 * bv.x; acc[1][1] += a1 * bv.y;
            acc[1][2] += a1 * bv.z; acc[1][3] += a1 * bv.w;
        }

        const int kbase = kt * KT + cg * 4;
        #pragma unroll
        for (int i = 0; i < 2; ++i) {
            int q = q0 + i;
            const int* mrow = Mb + (size_t)q * Ss + kbase;
            float* srow = sS + q * SROW + kbase;
            #pragma unroll
            for (int j = 0; j < 4; ++j) {
                float v = acc[i][j] * 0.125f;           // 1/sqrt(64)
                srow[j] = (mrow[j] == 0) ? -INFINITY : v;
            }
        }
    }
    __syncthreads();

    // ---------------- softmax + dropout (8 lanes per row, stride-8 cols) -------
    {
        const int row = tid >> 3;       // 0..31
        const int seg = tid & 7;        // 0..7
        float* rbase = sS + row * SROW;

        float m = -INFINITY;
        #pragma unroll 8
        for (int j = 0; j < 128; ++j) m = fmaxf(m, rbase[seg + 8 * j]);
        m = fmaxf(m, __shfl_xor_sync(0xffffffffu, m, 1));
        m = fmaxf(m, __shfl_xor_sync(0xffffffffu, m, 2));
        m = fmaxf(m, __shfl_xor_sync(0xffffffffu, m, 4));

        float ssum = 0.f;
        #pragma unroll 8
        for (int j = 0; j < 128; ++j) {
            int c = seg + 8 * j;
            float e = __expf(rbase[c] - m);
            rbase[c] = e;
            ssum += e;
        }
        ssum += __shfl_xor_sync(0xffffffffu, ssum, 1);
        ssum += __shfl_xor_sync(0xffffffffu, ssum, 2);
        ssum += __shfl_xor_sync(0xffffffffu, ssum, 4);
        const float inv = 1.0f / ssum;

        // dropout: keep iff jax_uniform(idx) < 0.9f ; scale kept by 1/0.9
        const uint32_t base = ((uint32_t)bh * Ss + (uint32_t)(qt * BQ + row)) * Ss;
        const float invkeep = 1.0f / 0.9f;
        for (int j = 0; j < 128; ++j) {
            int c = seg + 8 * j;
            float w = rbase[c] * inv;
            float u = jax_uniform(base + (uint32_t)c, rk0, rk1);
            rbase[c] = (u < 0.9f) ? w * invkeep : 0.0f;
        }
    }
    __syncthreads();

    // ---------------- write attn_weights (coalesced float4) ----------------
    {
        float* Aout = Attn + ((size_t)bh * Ss + (size_t)qt * BQ) * Ss;
        for (int i = tid; i < BQ * (Ss / 4); i += NTHREADS) {
            int row = i >> 8;                 // Ss/4 = 256 float4 per row
            int c4  = i & 255;
            ((float4*)(Aout + (size_t)row * Ss))[c4] =
                ((const float4*)(sS + row * SROW))[c4];
        }
    }

    // ---------------- PV: out = attn @ V ----------------
    float oacc[2][4] = {{0.f,0.f,0.f,0.f},{0.f,0.f,0.f,0.f}};
    for (int kt = 0; kt < Ss / KT; ++kt) {
        __syncthreads();
        // load V tile row-major: sT[k][d]
        {
            const float4* src = (const float4*)(Vb + (size_t)kt * KT * Dd);
            float4* dst = (float4*)sT;
            for (int i = tid; i < KT * Dd / 4; i += NTHREADS) dst[i] = src[i];
        }
        __syncthreads();

        #pragma unroll 16
        for (int k = 0; k < KT; ++k) {
            float a0 = sS[q0 * SROW + kt * KT + k];
            float a1 = sS[q1 * SROW + kt * KT + k];
            float4 bv = ((const float4*)(sT + k * Dd))[cg];
            oacc[0][0] += a0 * bv.x; oacc[0][1] += a0 * bv.y;
            oacc[0][2] += a0 * bv.z; oacc[0][3] += a0 * bv.w;
            oacc[1][0] += a1 * bv.x; oacc[1][1] += a1 * bv.y;
            oacc[1][2] += a1 * bv.z; oacc[1][3] += a1 * bv.w;
        }
    }

    {
        float* Ob = Out + ((size_t)bh * Ss + (size_t)qt * BQ) * Dd;
        ((float4*)(Ob + (size_t)q0 * Dd))[cg] =
            make_float4(oacc[0][0], oacc[0][1], oacc[0][2], oacc[0][3]);
        ((float4*)(Ob + (size_t)q1 * Dd))[cg] =
            make_float4(oacc[1][0], oacc[1][1], oacc[1][2], oacc[1][3]);
    }
}

extern "C" void kernel_launch(void* const* d_in, const int* in_sizes, int n_in,
                              void* d_out, int out_size) {
    const float* Q = (const float*)d_in[0];
    const float* K = (const float*)d_in[1];
    const float* V = (const float*)d_in[2];
    const int*   M = (const int*)d_in[3];

    float* out  = (float*)d_out;                                   // [B,H,S,D]
    float* attn = out + (size_t)Bb * Hh * Ss * Dd;                 // [B,H,S,S]

    // JAX: fold_in(key(42), 7) == threefry2x32((0,42), (0,7))
    constexpr K2 DK = threefry_host(0u, 42u, 0u, 7u);

    constexpr size_t SMEM_BYTES = (size_t)SMEM_FLOATS * sizeof(float);
    cudaFuncSetAttribute(attn_kernel,
                         cudaFuncAttributeMaxDynamicSharedMemorySize,
                         (int)SMEM_BYTES);

    dim3 grid(Ss / BQ, Hh, Bb);   // (32, 16, 8)
    attn_kernel<<<grid, NTHREADS, SMEM_BYTES>>>(Q, K, V, M, out, attn, DK.a, DK.b);
}

// round 4
// speedup vs baseline: 1.1740x; 1.1740x over previous
#include <cuda_runtime.h>
#include <cstdint>

// Problem constants: B=8, H=16, S=1024, D=64.
#define Bb 8
#define Hh 16
#define Ss 1024
#define Dd 64
#define BQ 32        // query rows per CTA
#define NTHREADS 256
#define SROW 1032    // padded smem stride for score tile
#define QS 65        // padded stride for Q tile
#define KS 65        // padded stride for K/V chunk

struct K2 { uint32_t a, b; };

__host__ __device__ constexpr uint32_t rotl_c(uint32_t x, int r) {
    return (x << r) | (x >> (32 - r));
}

// constexpr threefry2x32 for compile-time folded key
constexpr K2 threefry_host(uint32_t k0, uint32_t k1, uint32_t c0, uint32_t c1) {
    uint32_t ks[3] = { k0, k1, 0x1BD11BDAu ^ k0 ^ k1 };
    uint32_t x0 = c0 + ks[0], x1 = c1 + ks[1];
    const int rot[8] = {13, 15, 26, 6, 17, 29, 16, 24};
    for (int g = 0; g < 5; ++g) {
        for (int i = 0; i < 4; ++i) {
            x0 += x1;
            x1 = rotl_c(x1, rot[(g & 1) * 4 + i]);
            x1 ^= x0;
        }
        x0 += ks[(g + 1) % 3];
        x1 += ks[(g + 2) % 3] + (uint32_t)(g + 1);
    }
    return { x0, x1 };
}

// JAX partitionable threefry: counter (0, idx), bits = x0 ^ x1
__device__ __forceinline__ float jax_uniform(uint32_t idx, uint32_t k0, uint32_t k1) {
    const uint32_t ks2 = 0x1BD11BDAu ^ k0 ^ k1;
    uint32_t x0 = k0;
    uint32_t x1 = idx + k1;
#define TF_RND(r) { x0 += x1; x1 = __funnelshift_l(x1, x1, (r)); x1 ^= x0; }
    TF_RND(13) TF_RND(15) TF_RND(26) TF_RND(6)   x0 += k1;  x1 += ks2 + 1u;
    TF_RND(17) TF_RND(29) TF_RND(16) TF_RND(24)  x0 += ks2; x1 += k0 + 2u;
    TF_RND(13) TF_RND(15) TF_RND(26) TF_RND(6)   x0 += k0;  x1 += k1 + 3u;
    TF_RND(17) TF_RND(29) TF_RND(16) TF_RND(24)  x0 += k1;  x1 += ks2 + 4u;
    TF_RND(13) TF_RND(15) TF_RND(26) TF_RND(6)   x0 += ks2; x1 += k0 + 5u;
#undef TF_RND
    uint32_t bits = x0 ^ x1;
    return __uint_as_float((bits >> 9) | 0x3f800000u) - 1.0f;
}

__device__ __forceinline__ uint32_t f2tf(float x) {
    uint32_t r;
    asm("cvt.rna.tf32.f32 %0, %1;" : "=r"(r) : "f"(x));
    return r;
}

#define MMA_TF32(d0,d1,d2,d3,a0,a1,a2,a3,b0,b1)                               \
    asm volatile("mma.sync.aligned.m16n8k8.row.col.f32.tf32.tf32.f32 "        \
                 "{%0,%1,%2,%3},{%4,%5,%6,%7},{%8,%9},{%0,%1,%2,%3};"         \
                 : "+f"(d0), "+f"(d1), "+f"(d2), "+f"(d3)                     \
                 : "r"(a0), "r"(a1), "r"(a2), "r"(a3), "r"(b0), "r"(b1))

// smem layout (floats): sS[32*SROW] | sQ[32*QS] | sK[64*KS]
#define SMEM_FLOATS (BQ * SROW + BQ * QS + 64 * KS)

extern "C" __global__ void __launch_bounds__(NTHREADS, 1)
attn_kernel(const float* __restrict__ Q, const float* __restrict__ Kt,
            const float* __restrict__ V, const int* __restrict__ M,
            float* __restrict__ Out, float* __restrict__ Attn,
            uint32_t rk0, uint32_t rk1)
{
    extern __shared__ float smem[];
    float* sS = smem;
    float* sQ = smem + BQ * SROW;
    float* sK = sQ + BQ * QS;

    const int qt  = blockIdx.x;
    const int h   = blockIdx.y;
    const int b   = blockIdx.z;
    const int tid = threadIdx.x;
    const int bh  = b * Hh + h;

    const int w    = tid >> 5;
    const int lane = tid & 31;
    const int g    = lane >> 2;   // group 0..7
    const int tig  = lane & 3;    // thread-in-group
    const int mb   = (w & 1) * 16;  // m-tile base row (0 or 16)
    const int wg   = w >> 1;        // 0..3 -> n8 tiles {wg, wg+4}

    const float* Qb = Q  + ((size_t)bh * Ss + qt * BQ) * Dd;
    const float* Kb = Kt + (size_t)bh * Ss * Dd;
    const float* Vb = V  + (size_t)bh * Ss * Dd;
    const int*   Mb = M  + ((size_t)b * Ss + qt * BQ) * Ss;

    // ---- load Q tile, pre-scaled by 1/sqrt(64) ----
    for (int i = tid; i < BQ * Dd; i += NTHREADS) {
        int row = i >> 6, d = i & 63;
        sQ[row * QS + d] = Qb[i] * 0.125f;
    }
    __syncthreads();

    // ---- persistent A fragments (Q), hi/lo split for 3xTF32 ----
    // PTX m16n8k8 A layout: a0=A[g][tig], a1=A[g+8][tig], a2=A[g][tig+4], a3=A[g+8][tig+4]
    uint32_t ahi[8][4], alo[8][4];
    #pragma unroll
    for (int ks = 0; ks < 8; ++ks) {
        int c0 = ks * 8 + tig;
        float v0 = sQ[(mb + g) * QS + c0];          // a0: row g,   col tig
        float v1 = sQ[(mb + g + 8) * QS + c0];      // a1: row g+8, col tig
        float v2 = sQ[(mb + g) * QS + c0 + 4];      // a2: row g,   col tig+4
        float v3 = sQ[(mb + g + 8) * QS + c0 + 4];  // a3: row g+8, col tig+4
        ahi[ks][0] = f2tf(v0); alo[ks][0] = __float_as_uint(v0 - __uint_as_float(ahi[ks][0]));
        ahi[ks][1] = f2tf(v1); alo[ks][1] = __float_as_uint(v1 - __uint_as_float(ahi[ks][1]));
        ahi[ks][2] = f2tf(v2); alo[ks][2] = __float_as_uint(v2 - __uint_as_float(ahi[ks][2]));
        ahi[ks][3] = f2tf(v3); alo[ks][3] = __float_as_uint(v3 - __uint_as_float(ahi[ks][3]));
    }

    // ---------------- QK^T (3xTF32 mma) ----------------
    for (int nt = 0; nt < Ss / 64; ++nt) {
        __syncthreads();
        {
            const float4* src = (const float4*)(Kb + (size_t)nt * 64 * Dd);
            for (int i = tid; i < 64 * Dd / 4; i += NTHREADS) {
                float4 v = src[i];
                int key = i >> 4, d0 = (i & 15) * 4;
                float* p = sK + key * KS + d0;
                p[0] = v.x; p[1] = v.y; p[2] = v.z; p[3] = v.w;
            }
        }
        __syncthreads();

        #pragma unroll
        for (int s = 0; s < 2; ++s) {
            const int nb = (wg + 4 * s) * 8;
            float d0 = 0.f, d1 = 0.f, d2 = 0.f, d3 = 0.f;
            #pragma unroll
            for (int ks = 0; ks < 8; ++ks) {
                // B (col-major 8x8): b0 = B[tig][g] = K[nb+g][ks*8+tig], b1 = B[tig+4][g]
                float bv0 = sK[(nb + g) * KS + ks * 8 + tig];
                float bv1 = sK[(nb + g) * KS + ks * 8 + tig + 4];
                uint32_t bh0 = f2tf(bv0);
                uint32_t bl0 = __float_as_uint(bv0 - __uint_as_float(bh0));
                uint32_t bh1 = f2tf(bv1);
                uint32_t bl1 = __float_as_uint(bv1 - __uint_as_float(bh1));
                MMA_TF32(d0,d1,d2,d3, ahi[ks][0],ahi[ks][1],ahi[ks][2],ahi[ks][3], bh0,bh1);
                MMA_TF32(d0,d1,d2,d3, ahi[ks][0],ahi[ks][1],ahi[ks][2],ahi[ks][3], bl0,bl1);
                MMA_TF32(d0,d1,d2,d3, alo[ks][0],alo[ks][1],alo[ks][2],alo[ks][3], bh0,bh1);
            }
            // epilogue: mask + store to score tile
            // C layout: c0=C[g][2tig], c1=C[g][2tig+1], c2=C[g+8][2tig], c3=C[g+8][2tig+1]
            const int colg = nt * 64 + nb + tig * 2;
            const int r0 = mb + g, r1 = r0 + 8;
            int2 m0 = *(const int2*)(Mb + (size_t)r0 * Ss + colg);
            int2 m1 = *(const int2*)(Mb + (size_t)r1 * Ss + colg);
            sS[r0 * SROW + colg]     = m0.x ? d0 : -INFINITY;
            sS[r0 * SROW + colg + 1] = m0.y ? d1 : -INFINITY;
            sS[r1 * SROW + colg]     = m1.x ? d2 : -INFINITY;
            sS[r1 * SROW + colg + 1] = m1.y ? d3 : -INFINITY;
        }
    }
    __syncthreads();

    // ---------------- softmax + dropout ----------------
    {
        const int row = tid >> 3;
        const int seg = tid & 7;
        float* rbase = sS + row * SROW;

        float m = -INFINITY;
        #pragma unroll 8
        for (int j = 0; j < 128; ++j) m = fmaxf(m, rbase[seg + 8 * j]);
        m = fmaxf(m, __shfl_xor_sync(0xffffffffu, m, 1));
        m = fmaxf(m, __shfl_xor_sync(0xffffffffu, m, 2));
        m = fmaxf(m, __shfl_xor_sync(0xffffffffu, m, 4));

        float ssum = 0.f;
        #pragma unroll 8
        for (int j = 0; j < 128; ++j) {
            int c = seg + 8 * j;
            float e = __expf(rbase[c] - m);
            rbase[c] = e;
            ssum += e;
        }
        ssum += __shfl_xor_sync(0xffffffffu, ssum, 1);
        ssum += __shfl_xor_sync(0xffffffffu, ssum, 2);
        ssum += __shfl_xor_sync(0xffffffffu, ssum, 4);
        const float inv = 1.0f / ssum;

        const uint32_t base = ((uint32_t)bh * Ss + (uint32_t)(qt * BQ + row)) * Ss;
        const float invkeep = 1.0f / 0.9f;
        for (int j = 0; j < 128; ++j) {
            int c = seg + 8 * j;
            float wv = rbase[c] * inv;
            float u = jax_uniform(base + (uint32_t)c, rk0, rk1);
            rbase[c] = (u < 0.9f) ? wv * invkeep : 0.0f;
        }
    }
    __syncthreads();

    // ---------------- write attn_weights ----------------
    {
        float* Aout = Attn + ((size_t)bh * Ss + (size_t)qt * BQ) * Ss;
        for (int i = tid; i < BQ * (Ss / 4); i += NTHREADS) {
            int row = i >> 8;
            int c4  = i & 255;
            ((float4*)(Aout + (size_t)row * Ss))[c4] =
                ((const float4*)(sS + row * SROW))[c4];
        }
    }

    // ---------------- PV (3xTF32 mma) ----------------
    float o[2][4] = {{0.f,0.f,0.f,0.f},{0.f,0.f,0.f,0.f}};
    for (int kt = 0; kt < Ss / 64; ++kt) {
        __syncthreads();
        {
            const float4* src = (const float4*)(Vb + (size_t)kt * 64 * Dd);
            for (int i = tid; i < 64 * Dd / 4; i += NTHREADS) {
                float4 v = src[i];
                int key = i >> 4, d0 = (i & 15) * 4;
                float* p = sK + key * KS + d0;
                p[0] = v.x; p[1] = v.y; p[2] = v.z; p[3] = v.w;
            }
        }
        __syncthreads();

        #pragma unroll
        for (int s = 0; s < 2; ++s) {
            const int nb = (wg + 4 * s) * 8;
            #pragma unroll
            for (int ks = 0; ks < 8; ++ks) {
                const int colA = kt * 64 + ks * 8 + tig;
                // A layout: a0=P[g][tig], a1=P[g+8][tig], a2=P[g][tig+4], a3=P[g+8][tig+4]
                float a0v = sS[(mb + g) * SROW + colA];
                float a1v = sS[(mb + g + 8) * SROW + colA];
                float a2v = sS[(mb + g) * SROW + colA + 4];
                float a3v = sS[(mb + g + 8) * SROW + colA + 4];
                uint32_t A0h = f2tf(a0v), A1h = f2tf(a1v), A2h = f2tf(a2v), A3h = f2tf(a3v);
                uint32_t A0l = __float_as_uint(a0v - __uint_as_float(A0h));
                uint32_t A1l = __float_as_uint(a1v - __uint_as_float(A1h));
                uint32_t A2l = __float_as_uint(a2v - __uint_as_float(A2h));
                uint32_t A3l = __float_as_uint(a3v - __uint_as_float(A3h));

                const int krow = ks * 8 + tig;
                // B: b0 = V[krow][nb+g], b1 = V[krow+4][nb+g]
                float bv0 = sK[krow * KS + nb + g];
                float bv1 = sK[(krow + 4) * KS + nb + g];
                uint32_t bh0 = f2tf(bv0);
                uint32_t bl0 = __float_as_uint(bv0 - __uint_as_float(bh0));
                uint32_t bh1 = f2tf(bv1);
                uint32_t bl1 = __float_as_uint(bv1 - __uint_as_float(bh1));

                MMA_TF32(o[s][0],o[s][1],o[s][2],o[s][3], A0h,A1h,A2h,A3h, bh0,bh1);
                MMA_TF32(o[s][0],o[s][1],o[s][2],o[s][3], A0h,A1h,A2h,A3h, bl0,bl1);
                MMA_TF32(o[s][0],o[s][1],o[s][2],o[s][3], A0l,A1l,A2l,A3l, bh0,bh1);
            }
        }
    }

    // ---------------- write output ----------------
    {
        float* Ob = Out + ((size_t)bh * Ss + (size_t)qt * BQ) * Dd;
        #pragma unroll
        for (int s = 0; s < 2; ++s) {
            const int col = (wg + 4 * s) * 8 + tig * 2;
            *(float2*)(Ob + (size_t)(mb + g) * Dd + col)     = make_float2(o[s][0], o[s][1]);
            *(float2*)(Ob + (size_t)(mb + g + 8) * Dd + col) = make_float2(o[s][2], o[s][3]);
        }
    }
}

extern "C" void kernel_launch(void* const* d_in, const int* in_sizes, int n_in,
                              void* d_out, int out_size) {
    const float* Q = (const float*)d_in[0];
    const float* K = (const float*)d_in[1];
    const float* V = (const float*)d_in[2];
    const int*   M = (const int*)d_in[3];

    float* out  = (float*)d_out;
    float* attn = out + (size_t)Bb * Hh * Ss * Dd;

    constexpr K2 DK = threefry_host(0u, 42u, 0u, 7u);

    constexpr size_t SMEM_BYTES = (size_t)SMEM_FLOATS * sizeof(float);
    cudaFuncSetAttribute(attn_kernel,
                         cudaFuncAttributeMaxDynamicSharedMemorySize,
                         (int)SMEM_BYTES);

    dim3 grid(Ss / BQ, Hh, Bb);
    attn_kernel<<<grid, NTHREADS, SMEM_BYTES>>>(Q, K, V, M, out, attn, DK.a, DK.b);
}

// round 5
// speedup vs baseline: 3.0171x; 2.5700x over previous
#include <cuda_runtime.h>
#include <cstdint>

// Problem constants: B=8, H=16, S=1024, D=64.
#define Bb 8
#define Hh 16
#define Ss 1024
#define Dd 64

struct K2 { uint32_t a, b; };

__host__ __device__ constexpr uint32_t rotl_c(uint32_t x, int r) {
    return (x << r) | (x >> (32 - r));
}

// constexpr threefry2x32 for compile-time folded key
constexpr K2 threefry_host(uint32_t k0, uint32_t k1, uint32_t c0, uint32_t c1) {
    uint32_t ks[3] = { k0, k1, 0x1BD11BDAu ^ k0 ^ k1 };
    uint32_t x0 = c0 + ks[0], x1 = c1 + ks[1];
    const int rot[8] = {13, 15, 26, 6, 17, 29, 16, 24};
    for (int g = 0; g < 5; ++g) {
        for (int i = 0; i < 4; ++i) {
            x0 += x1;
            x1 = rotl_c(x1, rot[(g & 1) * 4 + i]);
            x1 ^= x0;
        }
        x0 += ks[(g + 1) % 3];
        x1 += ks[(g + 2) % 3] + (uint32_t)(g + 1);
    }
    return { x0, x1 };
}

// JAX partitionable threefry: counter (0, idx), bits = x0 ^ x1
__device__ __forceinline__ uint32_t jax_bits(uint32_t idx, uint32_t k0, uint32_t k1) {
    const uint32_t ks2 = 0x1BD11BDAu ^ k0 ^ k1;
    uint32_t x0 = k0;
    uint32_t x1 = idx + k1;
#define TF_RND(r) { x0 += x1; x1 = __funnelshift_l(x1, x1, (r)); x1 ^= x0; }
    TF_RND(13) TF_RND(15) TF_RND(26) TF_RND(6)   x0 += k1;  x1 += ks2 + 1u;
    TF_RND(17) TF_RND(29) TF_RND(16) TF_RND(24)  x0 += ks2; x1 += k0 + 2u;
    TF_RND(13) TF_RND(15) TF_RND(26) TF_RND(6)   x0 += k0;  x1 += k1 + 3u;
    TF_RND(17) TF_RND(29) TF_RND(16) TF_RND(24)  x0 += k1;  x1 += ks2 + 4u;
    TF_RND(13) TF_RND(15) TF_RND(26) TF_RND(6)   x0 += ks2; x1 += k0 + 5u;
#undef TF_RND
    return x0 ^ x1;
}
// keep iff uniform(bits) < 0.9f  ⟺  bits < 0xE6666600  (exact integer form)
#define KEEP_THRESH 0xE6666600u

__device__ __forceinline__ uint32_t f2tf(float x) {
    uint32_t r;
    asm("cvt.rna.tf32.f32 %0, %1;" : "=r"(r) : "f"(x));
    return r;
}

#define MMA_TF32(d0,d1,d2,d3,a0,a1,a2,a3,b0,b1)                               \
    asm volatile("mma.sync.aligned.m16n8k8.row.col.f32.tf32.tf32.f32 "        \
                 "{%0,%1,%2,%3},{%4,%5,%6,%7},{%8,%9},{%0,%1,%2,%3};"         \
                 : "+f"(d0), "+f"(d1), "+f"(d2), "+f"(d3)                     \
                 : "r"(a0), "r"(a1), "r"(a2), "r"(a3), "r"(b0), "r"(b1))

// ============================================================================
// K_A: scores = mask ? (Q K^T)/8 : -inf   -> Attn buffer
// CTA tile: 128 q-rows x 64 keys. grid (kt=16, qt=8, bh=128).
// smem: sQ[128*68] f32 (prescaled), sKh/sKl[64*68] (tf32 hi bits / f32 residual)
// ============================================================================
#define QKS 68
#define QK_SMEM_BYTES ((128 * QKS + 2 * 64 * QKS) * 4)

extern "C" __global__ void __launch_bounds__(256)
qk_kernel(const float* __restrict__ Q, const float* __restrict__ K,
          const int* __restrict__ M, float* __restrict__ Attn)
{
    extern __shared__ float sm[];
    float*    sQ  = sm;                                   // 128*68
    uint32_t* sKh = (uint32_t*)(sm + 128 * QKS);          // 64*68
    float*    sKl = (float*)(sKh + 64 * QKS);             // 64*68

    const int kt = blockIdx.x, qt = blockIdx.y, bh = blockIdx.z;
    const int b  = bh >> 4;
    const int tid = threadIdx.x;
    const int w = tid >> 5, lane = tid & 31, g = lane >> 2, tig = lane & 3;

    const float* Qg = Q + ((size_t)bh * Ss + qt * 128) * Dd;
    const float* Kg = K + ((size_t)bh * Ss + kt * 64) * Dd;

    for (int i = tid; i < 128 * 16; i += 256) {
        int row = i >> 4, c4 = (i & 15) * 4;
        float4 v = ((const float4*)Qg)[i];
        float* p = sQ + row * QKS + c4;
        p[0] = v.x * 0.125f; p[1] = v.y * 0.125f;
        p[2] = v.z * 0.125f; p[3] = v.w * 0.125f;
    }
    for (int i = tid; i < 64 * 16; i += 256) {
        int row = i >> 4, c4 = (i & 15) * 4;
        float4 v = ((const float4*)Kg)[i];
        uint32_t* ph = sKh + row * QKS + c4;
        float*    pl = sKl + row * QKS + c4;
        uint32_t h0 = f2tf(v.x), h1 = f2tf(v.y), h2 = f2tf(v.z), h3 = f2tf(v.w);
        ph[0] = h0; ph[1] = h1; ph[2] = h2; ph[3] = h3;
        pl[0] = v.x - __uint_as_float(h0); pl[1] = v.y - __uint_as_float(h1);
        pl[2] = v.z - __uint_as_float(h2); pl[3] = v.w - __uint_as_float(h3);
    }
    __syncthreads();

    const int mblk = (w & 3) * 32;     // 4 m-blocks of 32
    const int nblk = (w >> 2) * 32;    // 2 n-blocks of 32

    float acc[2][4][4];
    #pragma unroll
    for (int mt = 0; mt < 2; ++mt)
        #pragma unroll
        for (int nt = 0; nt < 4; ++nt)
            #pragma unroll
            for (int j = 0; j < 4; ++j) acc[mt][nt][j] = 0.f;

    #pragma unroll
    for (int ks = 0; ks < 8; ++ks) {
        uint32_t Ah[2][4], Al[2][4];
        #pragma unroll
        for (int mt = 0; mt < 2; ++mt) {
            const int r = mblk + mt * 16;
            const int c = ks * 8 + tig;
            float v0 = sQ[(r + g) * QKS + c];
            float v1 = sQ[(r + g + 8) * QKS + c];
            float v2 = sQ[(r + g) * QKS + c + 4];
            float v3 = sQ[(r + g + 8) * QKS + c + 4];
            Ah[mt][0] = f2tf(v0); Al[mt][0] = __float_as_uint(v0 - __uint_as_float(Ah[mt][0]));
            Ah[mt][1] = f2tf(v1); Al[mt][1] = __float_as_uint(v1 - __uint_as_float(Ah[mt][1]));
            Ah[mt][2] = f2tf(v2); Al[mt][2] = __float_as_uint(v2 - __uint_as_float(Ah[mt][2]));
            Ah[mt][3] = f2tf(v3); Al[mt][3] = __float_as_uint(v3 - __uint_as_float(Ah[mt][3]));
        }
        #pragma unroll
        for (int nt = 0; nt < 4; ++nt) {
            const int n = nblk + nt * 8 + g;
            const int c = ks * 8 + tig;
            uint32_t bh0 = sKh[n * QKS + c];
            uint32_t bh1 = sKh[n * QKS + c + 4];
            uint32_t bl0 = __float_as_uint(sKl[n * QKS + c]);
            uint32_t bl1 = __float_as_uint(sKl[n * QKS + c + 4]);
            #pragma unroll
            for (int mt = 0; mt < 2; ++mt) {
                MMA_TF32(acc[mt][nt][0],acc[mt][nt][1],acc[mt][nt][2],acc[mt][nt][3],
                         Ah[mt][0],Ah[mt][1],Ah[mt][2],Ah[mt][3], bh0,bh1);
                MMA_TF32(acc[mt][nt][0],acc[mt][nt][1],acc[mt][nt][2],acc[mt][nt][3],
                         Ah[mt][0],Ah[mt][1],Ah[mt][2],Ah[mt][3], bl0,bl1);
                MMA_TF32(acc[mt][nt][0],acc[mt][nt][1],acc[mt][nt][2],acc[mt][nt][3],
                         Al[mt][0],Al[mt][1],Al[mt][2],Al[mt][3], bh0,bh1);
            }
        }
    }

    // epilogue: mask + store to gmem
    #pragma unroll
    for (int mt = 0; mt < 2; ++mt) {
        #pragma unroll
        for (int nt = 0; nt < 4; ++nt) {
            const int gr0 = qt * 128 + mblk + mt * 16 + g;
            const int gr1 = gr0 + 8;
            const int gc  = kt * 64 + nblk + nt * 8 + tig * 2;
            int2 m0 = *(const int2*)(M + ((size_t)b * Ss + gr0) * Ss + gc);
            int2 m1 = *(const int2*)(M + ((size_t)b * Ss + gr1) * Ss + gc);
            float2 s0 = make_float2(m0.x ? acc[mt][nt][0] : -INFINITY,
                                    m0.y ? acc[mt][nt][1] : -INFINITY);
            float2 s1 = make_float2(m1.x ? acc[mt][nt][2] : -INFINITY,
                                    m1.y ? acc[mt][nt][3] : -INFINITY);
            *(float2*)(Attn + ((size_t)bh * Ss + gr0) * Ss + gc) = s0;
            *(float2*)(Attn + ((size_t)bh * Ss + gr1) * Ss + gc) = s1;
        }
    }
}

// ============================================================================
// K_B: in-place softmax + dropout over Attn rows. One warp per row.
// ============================================================================
extern "C" __global__ void __launch_bounds__(256)
softmax_kernel(float* __restrict__ Attn, uint32_t rk0, uint32_t rk1)
{
    const int w = threadIdx.x >> 5;
    const int lane = threadIdx.x & 31;
    const uint32_t row = blockIdx.x * 8 + w;
    float* R = Attn + (size_t)row * Ss;

    float4 v[8];
    #pragma unroll
    for (int j = 0; j < 8; ++j) v[j] = ((const float4*)R)[lane + 32 * j];

    float m = -INFINITY;
    #pragma unroll
    for (int j = 0; j < 8; ++j) {
        m = fmaxf(m, fmaxf(fmaxf(v[j].x, v[j].y), fmaxf(v[j].z, v[j].w)));
    }
    m = fmaxf(m, __shfl_xor_sync(0xffffffffu, m, 1));
    m = fmaxf(m, __shfl_xor_sync(0xffffffffu, m, 2));
    m = fmaxf(m, __shfl_xor_sync(0xffffffffu, m, 4));
    m = fmaxf(m, __shfl_xor_sync(0xffffffffu, m, 8));
    m = fmaxf(m, __shfl_xor_sync(0xffffffffu, m, 16));

    float s = 0.f;
    #pragma unroll
    for (int j = 0; j < 8; ++j) {
        v[j].x = __expf(v[j].x - m); v[j].y = __expf(v[j].y - m);
        v[j].z = __expf(v[j].z - m); v[j].w = __expf(v[j].w - m);
        s += (v[j].x + v[j].y) + (v[j].z + v[j].w);
    }
    s += __shfl_xor_sync(0xffffffffu, s, 1);
    s += __shfl_xor_sync(0xffffffffu, s, 2);
    s += __shfl_xor_sync(0xffffffffu, s, 4);
    s += __shfl_xor_sync(0xffffffffu, s, 8);
    s += __shfl_xor_sync(0xffffffffu, s, 16);

    const float inv = (1.0f / 0.9f) / s;
    const uint32_t rbase = (row << 10) + 4 * lane;

    #pragma unroll 2
    for (int j = 0; j < 8; ++j) {
        const uint32_t i0 = rbase + 128 * j;
        uint32_t b0 = jax_bits(i0 + 0, rk0, rk1);
        uint32_t b1 = jax_bits(i0 + 1, rk0, rk1);
        uint32_t b2 = jax_bits(i0 + 2, rk0, rk1);
        uint32_t b3 = jax_bits(i0 + 3, rk0, rk1);
        v[j].x = (b0 < KEEP_THRESH) ? v[j].x * inv : 0.f;
        v[j].y = (b1 < KEEP_THRESH) ? v[j].y * inv : 0.f;
        v[j].z = (b2 < KEEP_THRESH) ? v[j].z * inv : 0.f;
        v[j].w = (b3 < KEEP_THRESH) ? v[j].w * inv : 0.f;
        ((float4*)R)[lane + 32 * j] = v[j];
    }
}

// ============================================================================
// K_C: Out = Attn @ V. CTA: 128 q-rows x 64 d. grid (qt=8, bh=128).
// smem: sP[128*68] f32, sVh/sVl[64*72]
// ============================================================================
#define PVS 68
#define PVV 72
#define PV_SMEM_BYTES ((128 * PVS + 2 * 64 * PVV) * 4)

extern "C" __global__ void __launch_bounds__(256)
pv_kernel(const float* __restrict__ Attn, const float* __restrict__ V,
          float* __restrict__ Out)
{
    extern __shared__ float sm[];
    float*    sP  = sm;                                   // 128*68
    uint32_t* sVh = (uint32_t*)(sm + 128 * PVS);          // 64*72
    float*    sVl = (float*)(sVh + 64 * PVV);             // 64*72

    const int qt = blockIdx.x, bh = blockIdx.y;
    const int tid = threadIdx.x;
    const int w = tid >> 5, lane = tid & 31, g = lane >> 2, tig = lane & 3;

    const float* Ag = Attn + ((size_t)bh * Ss + qt * 128) * Ss;
    const float* Vg = V + (size_t)bh * Ss * Dd;

    float acc[8][4];
    #pragma unroll
    for (int nt = 0; nt < 8; ++nt)
        #pragma unroll
        for (int j = 0; j < 4; ++j) acc[nt][j] = 0.f;

    for (int kt = 0; kt < 16; ++kt) {
        __syncthreads();
        for (int i = tid; i < 128 * 16; i += 256) {
            int row = i >> 4, c4 = (i & 15) * 4;
            float4 v = *(const float4*)(Ag + (size_t)row * Ss + kt * 64 + c4);
            float* p = sP + row * PVS + c4;
            p[0] = v.x; p[1] = v.y; p[2] = v.z; p[3] = v.w;
        }
        for (int i = tid; i < 64 * 16; i += 256) {
            int row = i >> 4, c4 = (i & 15) * 4;
            float4 v = ((const float4*)(Vg + (size_t)(kt * 64 + row) * Dd))[(i & 15)];
            uint32_t* ph = sVh + row * PVV + c4;
            float*    pl = sVl + row * PVV + c4;
            uint32_t h0 = f2tf(v.x), h1 = f2tf(v.y), h2 = f2tf(v.z), h3 = f2tf(v.w);
            ph[0] = h0; ph[1] = h1; ph[2] = h2; ph[3] = h3;
            pl[0] = v.x - __uint_as_float(h0); pl[1] = v.y - __uint_as_float(h1);
            pl[2] = v.z - __uint_as_float(h2); pl[3] = v.w - __uint_as_float(h3);
        }
        __syncthreads();

        #pragma unroll
        for (int ks = 0; ks < 8; ++ks) {
            const int c = ks * 8 + tig;
            float v0 = sP[(w * 16 + g) * PVS + c];
            float v1 = sP[(w * 16 + g + 8) * PVS + c];
            float v2 = sP[(w * 16 + g) * PVS + c + 4];
            float v3 = sP[(w * 16 + g + 8) * PVS + c + 4];
            uint32_t A0h = f2tf(v0), A1h = f2tf(v1), A2h = f2tf(v2), A3h = f2tf(v3);
            uint32_t A0l = __float_as_uint(v0 - __uint_as_float(A0h));
            uint32_t A1l = __float_as_uint(v1 - __uint_as_float(A1h));
            uint32_t A2l = __float_as_uint(v2 - __uint_as_float(A2h));
            uint32_t A3l = __float_as_uint(v3 - __uint_as_float(A3h));

            #pragma unroll
            for (int nt = 0; nt < 8; ++nt) {
                const int col = nt * 8 + g;
                uint32_t bh0 = sVh[(ks * 8 + tig) * PVV + col];
                uint32_t bh1 = sVh[(ks * 8 + tig + 4) * PVV + col];
                uint32_t bl0 = __float_as_uint(sVl[(ks * 8 + tig) * PVV + col]);
                uint32_t bl1 = __float_as_uint(sVl[(ks * 8 + tig + 4) * PVV + col]);
                MMA_TF32(acc[nt][0],acc[nt][1],acc[nt][2],acc[nt][3],
                         A0h,A1h,A2h,A3h, bh0,bh1);
                MMA_TF32(acc[nt][0],acc[nt][1],acc[nt][2],acc[nt][3],
                         A0h,A1h,A2h,A3h, bl0,bl1);
                MMA_TF32(acc[nt][0],acc[nt][1],acc[nt][2],acc[nt][3],
                         A0l,A1l,A2l,A3l, bh0,bh1);
            }
        }
    }

    const int gr0 = qt * 128 + w * 16 + g;
    const int gr1 = gr0 + 8;
    float* Ob = Out + (size_t)bh * Ss * Dd;
    #pragma unroll
    for (int nt = 0; nt < 8; ++nt) {
        const int col = nt * 8 + tig * 2;
        *(float2*)(Ob + (size_t)gr0 * Dd + col) = make_float2(acc[nt][0], acc[nt][1]);
        *(float2*)(Ob + (size_t)gr1 * Dd + col) = make_float2(acc[nt][2], acc[nt][3]);
    }
}

// ============================================================================
extern "C" void kernel_launch(void* const* d_in, const int* in_sizes, int n_in,
                              void* d_out, int out_size) {
    const float* Q = (const float*)d_in[0];
    const float* K = (const float*)d_in[1];
    const float* V = (const float*)d_in[2];
    const int*   M = (const int*)d_in[3];

    float* out  = (float*)d_out;
    float* attn = out + (size_t)Bb * Hh * Ss * Dd;

    constexpr K2 DK = threefry_host(0u, 42u, 0u, 7u);

    static bool configured = false;
    if (!configured) {
        cudaFuncSetAttribute(qk_kernel, cudaFuncAttributeMaxDynamicSharedMemorySize,
                             QK_SMEM_BYTES);
        cudaFuncSetAttribute(pv_kernel, cudaFuncAttributeMaxDynamicSharedMemorySize,
                             PV_SMEM_BYTES);
        configured = true;
    }

    qk_kernel<<<dim3(16, 8, 128), 256, QK_SMEM_BYTES>>>(Q, K, M, attn);
    softmax_kernel<<<(Bb * Hh * Ss) / 8, 256>>>(attn, DK.a, DK.b);
    pv_kernel<<<dim3(8, 128), 256, PV_SMEM_BYTES>>>(attn, V, out);
}

// round 6
// speedup vs baseline: 3.2527x; 1.0781x over previous
#include <cuda_runtime.h>
#include <cstdint>

// Problem constants: B=8, H=16, S=1024, D=64.
#define Bb 8
#define Hh 16
#define Ss 1024
#define Dd 64

struct K2 { uint32_t a, b; };

__host__ __device__ constexpr uint32_t rotl_c(uint32_t x, int r) {
    return (x << r) | (x >> (32 - r));
}

// constexpr threefry2x32 for compile-time folded key
constexpr K2 threefry_host(uint32_t k0, uint32_t k1, uint32_t c0, uint32_t c1) {
    uint32_t ks[3] = { k0, k1, 0x1BD11BDAu ^ k0 ^ k1 };
    uint32_t x0 = c0 + ks[0], x1 = c1 + ks[1];
    const int rot[8] = {13, 15, 26, 6, 17, 29, 16, 24};
    for (int g = 0; g < 5; ++g) {
        for (int i = 0; i < 4; ++i) {
            x0 += x1;
            x1 = rotl_c(x1, rot[(g & 1) * 4 + i]);
            x1 ^= x0;
        }
        x0 += ks[(g + 1) % 3];
        x1 += ks[(g + 2) % 3] + (uint32_t)(g + 1);
    }
    return { x0, x1 };
}

// JAX partitionable threefry: counter (0, idx), bits = x0 ^ x1
__device__ __forceinline__ uint32_t jax_bits(uint32_t idx, uint32_t k0, uint32_t k1) {
    const uint32_t ks2 = 0x1BD11BDAu ^ k0 ^ k1;
    uint32_t x0 = k0;
    uint32_t x1 = idx + k1;
#define TF_RND(r) { x0 += x1; x1 = __funnelshift_l(x1, x1, (r)); x1 ^= x0; }
    TF_RND(13) TF_RND(15) TF_RND(26) TF_RND(6)   x0 += k1;  x1 += ks2 + 1u;
    TF_RND(17) TF_RND(29) TF_RND(16) TF_RND(24)  x0 += ks2; x1 += k0 + 2u;
    TF_RND(13) TF_RND(15) TF_RND(26) TF_RND(6)   x0 += k0;  x1 += k1 + 3u;
    TF_RND(17) TF_RND(29) TF_RND(16) TF_RND(24)  x0 += k1;  x1 += ks2 + 4u;
    TF_RND(13) TF_RND(15) TF_RND(26) TF_RND(6)   x0 += ks2; x1 += k0 + 5u;
#undef TF_RND
    return x0 ^ x1;
}
// keep iff uniform(bits) < 0.9f  ⟺  bits < 0xE6666600  (exact integer form)
#define KEEP_THRESH 0xE6666600u

__device__ __forceinline__ uint32_t f2tf(float x) {
    uint32_t r;
    asm("cvt.rna.tf32.f32 %0, %1;" : "=r"(r) : "f"(x));
    return r;
}

#define MMA_TF32(d0,d1,d2,d3,a0,a1,a2,a3,b0,b1)                               \
    asm volatile("mma.sync.aligned.m16n8k8.row.col.f32.tf32.tf32.f32 "        \
                 "{%0,%1,%2,%3},{%4,%5,%6,%7},{%8,%9},{%0,%1,%2,%3};"         \
                 : "+f"(d0), "+f"(d1), "+f"(d2), "+f"(d3)                     \
                 : "r"(a0), "r"(a1), "r"(a2), "r"(a3), "r"(b0), "r"(b1))

// per-row exp-sum partials: [B*H*S rows][32 col-blocks of 32]
__device__ float g_rowsum[(size_t)Bb * Hh * Ss * 32];

// ============================================================================
// K_A: scores = mask ? (Q K^T)/8 : -inf -> Attn buffer, + partial exp-sums
// CTA tile: 128 q-rows x 64 keys. grid (kt=16, qt=8, bh=128).
// ============================================================================
#define QKS 68
#define QK_SMEM_BYTES ((128 * QKS + 2 * 64 * QKS) * 4)

extern "C" __global__ void __launch_bounds__(256)
qk_kernel(const float* __restrict__ Q, const float* __restrict__ K,
          const int* __restrict__ M, float* __restrict__ Attn)
{
    extern __shared__ float sm[];
    float*    sQ  = sm;                                   // 128*68
    uint32_t* sKh = (uint32_t*)(sm + 128 * QKS);          // 64*68
    float*    sKl = (float*)(sKh + 64 * QKS);             // 64*68

    const int kt = blockIdx.x, qt = blockIdx.y, bh = blockIdx.z;
    const int b  = bh >> 4;
    const int tid = threadIdx.x;
    const int w = tid >> 5, lane = tid & 31, g = lane >> 2, tig = lane & 3;

    const float* Qg = Q + ((size_t)bh * Ss + qt * 128) * Dd;
    const float* Kg = K + ((size_t)bh * Ss + kt * 64) * Dd;

    for (int i = tid; i < 128 * 16; i += 256) {
        int row = i >> 4, c4 = (i & 15) * 4;
        float4 v = ((const float4*)Qg)[i];
        float* p = sQ + row * QKS + c4;
        p[0] = v.x * 0.125f; p[1] = v.y * 0.125f;
        p[2] = v.z * 0.125f; p[3] = v.w * 0.125f;
    }
    for (int i = tid; i < 64 * 16; i += 256) {
        int row = i >> 4, c4 = (i & 15) * 4;
        float4 v = ((const float4*)Kg)[i];
        uint32_t* ph = sKh + row * QKS + c4;
        float*    pl = sKl + row * QKS + c4;
        uint32_t h0 = f2tf(v.x), h1 = f2tf(v.y), h2 = f2tf(v.z), h3 = f2tf(v.w);
        ph[0] = h0; ph[1] = h1; ph[2] = h2; ph[3] = h3;
        pl[0] = v.x - __uint_as_float(h0); pl[1] = v.y - __uint_as_float(h1);
        pl[2] = v.z - __uint_as_float(h2); pl[3] = v.w - __uint_as_float(h3);
    }
    __syncthreads();

    const int mblk = (w & 3) * 32;     // 4 m-blocks of 32
    const int nblk = (w >> 2) * 32;    // 2 n-blocks of 32

    float acc[2][4][4];
    #pragma unroll
    for (int mt = 0; mt < 2; ++mt)
        #pragma unroll
        for (int nt = 0; nt < 4; ++nt)
            #pragma unroll
            for (int j = 0; j < 4; ++j) acc[mt][nt][j] = 0.f;

    #pragma unroll
    for (int ks = 0; ks < 8; ++ks) {
        uint32_t Ah[2][4], Al[2][4];
        #pragma unroll
        for (int mt = 0; mt < 2; ++mt) {
            const int r = mblk + mt * 16;
            const int c = ks * 8 + tig;
            float v0 = sQ[(r + g) * QKS + c];
            float v1 = sQ[(r + g + 8) * QKS + c];
            float v2 = sQ[(r + g) * QKS + c + 4];
            float v3 = sQ[(r + g + 8) * QKS + c + 4];
            Ah[mt][0] = f2tf(v0); Al[mt][0] = __float_as_uint(v0 - __uint_as_float(Ah[mt][0]));
            Ah[mt][1] = f2tf(v1); Al[mt][1] = __float_as_uint(v1 - __uint_as_float(Ah[mt][1]));
            Ah[mt][2] = f2tf(v2); Al[mt][2] = __float_as_uint(v2 - __uint_as_float(Ah[mt][2]));
            Ah[mt][3] = f2tf(v3); Al[mt][3] = __float_as_uint(v3 - __uint_as_float(Ah[mt][3]));
        }
        #pragma unroll
        for (int nt = 0; nt < 4; ++nt) {
            const int n = nblk + nt * 8 + g;
            const int c = ks * 8 + tig;
            uint32_t bh0 = sKh[n * QKS + c];
            uint32_t bh1 = sKh[n * QKS + c + 4];
            uint32_t bl0 = __float_as_uint(sKl[n * QKS + c]);
            uint32_t bl1 = __float_as_uint(sKl[n * QKS + c + 4]);
            #pragma unroll
            for (int mt = 0; mt < 2; ++mt) {
                MMA_TF32(acc[mt][nt][0],acc[mt][nt][1],acc[mt][nt][2],acc[mt][nt][3],
                         Ah[mt][0],Ah[mt][1],Ah[mt][2],Ah[mt][3], bh0,bh1);
                MMA_TF32(acc[mt][nt][0],acc[mt][nt][1],acc[mt][nt][2],acc[mt][nt][3],
                         Ah[mt][0],Ah[mt][1],Ah[mt][2],Ah[mt][3], bl0,bl1);
                MMA_TF32(acc[mt][nt][0],acc[mt][nt][1],acc[mt][nt][2],acc[mt][nt][3],
                         Al[mt][0],Al[mt][1],Al[mt][2],Al[mt][3], bh0,bh1);
            }
        }
    }

    // epilogue: mask + store scores + per-warp partial exp-sums
    float rsum[2][2] = {{0.f, 0.f}, {0.f, 0.f}};
    #pragma unroll
    for (int mt = 0; mt < 2; ++mt) {
        #pragma unroll
        for (int nt = 0; nt < 4; ++nt) {
            const int gr0 = qt * 128 + mblk + mt * 16 + g;
            const int gr1 = gr0 + 8;
            const int gc  = kt * 64 + nblk + nt * 8 + tig * 2;
            int2 m0 = *(const int2*)(M + ((size_t)b * Ss + gr0) * Ss + gc);
            int2 m1 = *(const int2*)(M + ((size_t)b * Ss + gr1) * Ss + gc);
            float2 s0 = make_float2(m0.x ? acc[mt][nt][0] : -INFINITY,
                                    m0.y ? acc[mt][nt][1] : -INFINITY);
            float2 s1 = make_float2(m1.x ? acc[mt][nt][2] : -INFINITY,
                                    m1.y ? acc[mt][nt][3] : -INFINITY);
            rsum[mt][0] += (m0.x ? __expf(s0.x) : 0.f) + (m0.y ? __expf(s0.y) : 0.f);
            rsum[mt][1] += (m1.x ? __expf(s1.x) : 0.f) + (m1.y ? __expf(s1.y) : 0.f);
            *(float2*)(Attn + ((size_t)bh * Ss + gr0) * Ss + gc) = s0;
            *(float2*)(Attn + ((size_t)bh * Ss + gr1) * Ss + gc) = s1;
        }
    }
    // reduce over tig lanes (1,2 within the 4-lane group), then write partials
    const int cidx = kt * 2 + (nblk >> 5);
    #pragma unroll
    for (int mt = 0; mt < 2; ++mt) {
        float a = rsum[mt][0];
        a += __shfl_xor_sync(0xffffffffu, a, 1);
        a += __shfl_xor_sync(0xffffffffu, a, 2);
        float c = rsum[mt][1];
        c += __shfl_xor_sync(0xffffffffu, c, 1);
        c += __shfl_xor_sync(0xffffffffu, c, 2);
        if (tig == 0) {
            const uint32_t r0 = (uint32_t)(bh * Ss + qt * 128 + mblk + mt * 16 + g);
            g_rowsum[(size_t)r0 * 32 + cidx]       = a;
            g_rowsum[(size_t)(r0 + 8) * 32 + cidx] = c;
        }
    }
}

// ============================================================================
// K_B fused: softmax + dropout + attn write + PV.
// CTA: 128 q-rows x 64 d out. grid (qt=8, bh=128).
// ============================================================================
#define PVS 68
#define PVV 72
#define PV_SMEM_FLOATS (128 * PVS + 2 * 64 * PVV + 128)
#define PV_SMEM_BYTES (PV_SMEM_FLOATS * 4)

extern "C" __global__ void __launch_bounds__(256)
pv_kernel(float* __restrict__ Attn, const float* __restrict__ V,
          float* __restrict__ Out, uint32_t rk0, uint32_t rk1)
{
    extern __shared__ float sm[];
    float*    sP   = sm;                                   // 128*68
    uint32_t* sVh  = (uint32_t*)(sm + 128 * PVS);          // 64*72
    float*    sVl  = (float*)(sVh + 64 * PVV);             // 64*72
    float*    sInv = sVl + 64 * PVV;                       // 128

    const int qt = blockIdx.x, bh = blockIdx.y;
    const int tid = threadIdx.x;
    const int w = tid >> 5, lane = tid & 31, g = lane >> 2, tig = lane & 3;

    float* Ag = Attn + ((size_t)bh * Ss + qt * 128) * Ss;
    const float* Vg = V + (size_t)bh * Ss * Dd;

    // deterministic row-sum reduction from qk partials
    if (tid < 128) {
        const float4* p = (const float4*)(g_rowsum +
            ((size_t)(bh * Ss + qt * 128 + tid)) * 32);
        float s = 0.f;
        #pragma unroll
        for (int j = 0; j < 8; ++j) {
            float4 v = p[j];
            s += (v.x + v.y) + (v.z + v.w);
        }
        sInv[tid] = (1.0f / 0.9f) / s;
    }

    float acc[8][4];
    #pragma unroll
    for (int nt = 0; nt < 8; ++nt)
        #pragma unroll
        for (int j = 0; j < 4; ++j) acc[nt][j] = 0.f;

    const uint32_t rowg_base = (uint32_t)(bh * Ss + qt * 128);

    for (int kt = 0; kt < 16; ++kt) {
        __syncthreads();
        // load score tile -> exp * inv + dropout -> attn gmem + sP
        for (int i = tid; i < 128 * 16; i += 256) {
            int row = i >> 4, c4 = (i & 15) * 4;
            float* gp = Ag + (size_t)row * Ss + kt * 64 + c4;
            float4 v = *(const float4*)gp;
            const float inv = sInv[row];
            const uint32_t idx0 = ((rowg_base + row) << 10) + kt * 64 + c4;
            uint32_t b0 = jax_bits(idx0 + 0, rk0, rk1);
            uint32_t b1 = jax_bits(idx0 + 1, rk0, rk1);
            uint32_t b2 = jax_bits(idx0 + 2, rk0, rk1);
            uint32_t b3 = jax_bits(idx0 + 3, rk0, rk1);
            v.x = (b0 < KEEP_THRESH) ? __expf(v.x) * inv : 0.f;
            v.y = (b1 < KEEP_THRESH) ? __expf(v.y) * inv : 0.f;
            v.z = (b2 < KEEP_THRESH) ? __expf(v.z) * inv : 0.f;
            v.w = (b3 < KEEP_THRESH) ? __expf(v.w) * inv : 0.f;
            *(float4*)gp = v;
            float* p = sP + row * PVS + c4;
            p[0] = v.x; p[1] = v.y; p[2] = v.z; p[3] = v.w;
        }
        // load V tile, hi/lo presplit
        for (int i = tid; i < 64 * 16; i += 256) {
            int row = i >> 4, c4 = (i & 15) * 4;
            float4 v = ((const float4*)(Vg + (size_t)(kt * 64 + row) * Dd))[(i & 15)];
            uint32_t* ph = sVh + row * PVV + c4;
            float*    pl = sVl + row * PVV + c4;
            uint32_t h0 = f2tf(v.x), h1 = f2tf(v.y), h2 = f2tf(v.z), h3 = f2tf(v.w);
            ph[0] = h0; ph[1] = h1; ph[2] = h2; ph[3] = h3;
            pl[0] = v.x - __uint_as_float(h0); pl[1] = v.y - __uint_as_float(h1);
            pl[2] = v.z - __uint_as_float(h2); pl[3] = v.w - __uint_as_float(h3);
        }
        __syncthreads();

        #pragma unroll
        for (int ks = 0; ks < 8; ++ks) {
            const int c = ks * 8 + tig;
            float v0 = sP[(w * 16 + g) * PVS + c];
            float v1 = sP[(w * 16 + g + 8) * PVS + c];
            float v2 = sP[(w * 16 + g) * PVS + c + 4];
            float v3 = sP[(w * 16 + g + 8) * PVS + c + 4];
            uint32_t A0h = f2tf(v0), A1h = f2tf(v1), A2h = f2tf(v2), A3h = f2tf(v3);
            uint32_t A0l = __float_as_uint(v0 - __uint_as_float(A0h));
            uint32_t A1l = __float_as_uint(v1 - __uint_as_float(A1h));
            uint32_t A2l = __float_as_uint(v2 - __uint_as_float(A2h));
            uint32_t A3l = __float_as_uint(v3 - __uint_as_float(A3h));

            #pragma unroll
            for (int nt = 0; nt < 8; ++nt) {
                const int col = nt * 8 + g;
                uint32_t bh0 = sVh[(ks * 8 + tig) * PVV + col];
                uint32_t bh1 = sVh[(ks * 8 + tig + 4) * PVV + col];
                uint32_t bl0 = __float_as_uint(sVl[(ks * 8 + tig) * PVV + col]);
                uint32_t bl1 = __float_as_uint(sVl[(ks * 8 + tig + 4) * PVV + col]);
                MMA_TF32(acc[nt][0],acc[nt][1],acc[nt][2],acc[nt][3],
                         A0h,A1h,A2h,A3h, bh0,bh1);
                MMA_TF32(acc[nt][0],acc[nt][1],acc[nt][2],acc[nt][3],
                         A0h,A1h,A2h,A3h, bl0,bl1);
                MMA_TF32(acc[nt][0],acc[nt][1],acc[nt][2],acc[nt][3],
                         A0l,A1l,A2l,A3l, bh0,bh1);
            }
        }
    }

    const int gr0 = qt * 128 + w * 16 + g;
    const int gr1 = gr0 + 8;
    float* Ob = Out + (size_t)bh * Ss * Dd;
    #pragma unroll
    for (int nt = 0; nt < 8; ++nt) {
        const int col = nt * 8 + tig * 2;
        *(float2*)(Ob + (size_t)gr0 * Dd + col) = make_float2(acc[nt][0], acc[nt][1]);
        *(float2*)(Ob + (size_t)gr1 * Dd + col) = make_float2(acc[nt][2], acc[nt][3]);
    }
}

// ============================================================================
extern "C" void kernel_launch(void* const* d_in, const int* in_sizes, int n_in,
                              void* d_out, int out_size) {
    const float* Q = (const float*)d_in[0];
    const float* K = (const float*)d_in[1];
    const float* V = (const float*)d_in[2];
    const int*   M = (const int*)d_in[3];

    float* out  = (float*)d_out;
    float* attn = out + (size_t)Bb * Hh * Ss * Dd;

    constexpr K2 DK = threefry_host(0u, 42u, 0u, 7u);

    static bool configured = false;
    if (!configured) {
        cudaFuncSetAttribute(qk_kernel, cudaFuncAttributeMaxDynamicSharedMemorySize,
                             QK_SMEM_BYTES);
        cudaFuncSetAttribute(pv_kernel, cudaFuncAttributeMaxDynamicSharedMemorySize,
                             PV_SMEM_BYTES);
        configured = true;
    }

    qk_kernel<<<dim3(16, 8, 128), 256, QK_SMEM_BYTES>>>(Q, K, M, attn);
    pv_kernel<<<dim3(8, 128), 256, PV_SMEM_BYTES>>>(attn, V, out, DK.a, DK.b);
}